// round 2
// baseline (speedup 1.0000x reference)
#include <cuda_runtime.h>
#include <math.h>

#define BB 128   // batch
#define TT 100   // time
#define PD 4096  // proj dim
#define HG 512   // lstm gate dim
#define HD 128   // lstm hidden
#define GH 261   // gru hidden
#define GG 783   // gru gate dim
#define ZD 64    // latent
#define XD 256   // fcin out

// ---- scratch (no allocs allowed) ----
__device__ float g_proj[BB*TT*PD];     // (b*T+t, 4096)
__device__ float g_xg[TT*BB*HG];       // (t, b, 512)
__device__ float g_WhhT[HD*HG];        // (k, g) 128x512
__device__ float g_gWhhT[GH*GG];       // (k, g) 261x783
__device__ float g_hT[BB*HD];
__device__ float g_gxbase[BB*GG];

__device__ __forceinline__ float sigmoidf_(float x){ return 1.0f/(1.0f+expf(-x)); }
__device__ __forceinline__ float leakyf_(float x, float s){ return x >= 0.0f ? x : s*x; }

// K0: transpose recurrent weights for coalesced per-step loads
__global__ void k_prep(const float* __restrict__ lstm_Whh, const float* __restrict__ gru_Whh)
{
    int i = blockIdx.x*blockDim.x + threadIdx.x;
    int stride = gridDim.x*blockDim.x;
    for (int idx = i; idx < HG*HD; idx += stride) {
        int g = idx / HD, k = idx - g*HD;
        g_WhhT[k*HG + g] = lstm_Whh[idx];
    }
    for (int idx = i; idx < GG*GH; idx += stride) {
        int g = idx / GH, k = idx - g*GH;
        g_gWhhT[k*GG + g] = gru_Whh[idx];
    }
}

// K1: proj = leaky(pose @ proj_W^T + b, 0.1), one block per (b,t) row
__global__ void __launch_bounds__(512) k_proj(const float* __restrict__ pose,
                                              const float* __restrict__ W,
                                              const float* __restrict__ bias)
{
    __shared__ float p[9];
    int row = blockIdx.x;
    int tid = threadIdx.x;
    if (tid < 9) p[tid] = pose[row*9 + tid];
    __syncthreads();
#pragma unroll
    for (int i = 0; i < PD/512; i++) {
        int k = tid + i*512;
        const float* w = W + k*9;
        float acc = bias[k];
#pragma unroll
        for (int j = 0; j < 9; j++) acc += w[j]*p[j];
        g_proj[row*PD + k] = leakyf_(acc, 0.1f);
    }
}

// K2: x_gates = proj @ lstm_Wih^T + bih + bhh ; output layout (t,b,g)
#define GM 128
#define GN 128
#define GK 16
__global__ void __launch_bounds__(256, 2) k_gemm(const float* __restrict__ Wih,
                                                 const float* __restrict__ bih,
                                                 const float* __restrict__ bhh)
{
    __shared__ float As[GK][GM+4];
    __shared__ float Bs[GK][GN+4];
    int tid = threadIdx.x;
    int bm = blockIdx.x;   // 0..99
    int bn = blockIdx.y;   // 0..3
    int tx = tid & 15, ty = tid >> 4;
    float acc[8][8];
#pragma unroll
    for (int i = 0; i < 8; i++)
#pragma unroll
        for (int j = 0; j < 8; j++) acc[i][j] = 0.f;

    int lr = tid >> 2;          // 0..63
    int lk = (tid & 3) * 4;     // 0,4,8,12
    const float* Ag = g_proj + bm*GM*PD;
    const float* Wg = Wih + bn*GN*PD;

    for (int k0 = 0; k0 < PD; k0 += GK) {
#pragma unroll
        for (int r = 0; r < 2; r++) {
            int row = lr + r*64;
            float4 va = *(const float4*)(Ag + row*PD + k0 + lk);
            As[lk+0][row] = va.x; As[lk+1][row] = va.y;
            As[lk+2][row] = va.z; As[lk+3][row] = va.w;
            float4 vb = *(const float4*)(Wg + row*PD + k0 + lk);
            Bs[lk+0][row] = vb.x; Bs[lk+1][row] = vb.y;
            Bs[lk+2][row] = vb.z; Bs[lk+3][row] = vb.w;
        }
        __syncthreads();
#pragma unroll
        for (int k = 0; k < GK; k++) {
            float4 a0 = *(const float4*)&As[k][ty*8];
            float4 a1 = *(const float4*)&As[k][ty*8+4];
            float4 b0 = *(const float4*)&Bs[k][tx*8];
            float4 b1 = *(const float4*)&Bs[k][tx*8+4];
            float a[8] = {a0.x,a0.y,a0.z,a0.w,a1.x,a1.y,a1.z,a1.w};
            float b[8] = {b0.x,b0.y,b0.z,b0.w,b1.x,b1.y,b1.z,b1.w};
#pragma unroll
            for (int i = 0; i < 8; i++)
#pragma unroll
                for (int j = 0; j < 8; j++) acc[i][j] += a[i]*b[j];
        }
        __syncthreads();
    }
    // epilogue: add biases, scatter rows (b*T+t) -> (t,b,g)
    float bsum[8];
#pragma unroll
    for (int j = 0; j < 8; j++) {
        int g = bn*GN + tx*8 + j;
        bsum[j] = bih[g] + bhh[g];
    }
#pragma unroll
    for (int i = 0; i < 8; i++) {
        int row = bm*GM + ty*8 + i;
        int b = row / TT;
        int t = row - b*TT;
        float* o = g_xg + t*(BB*HG) + b*HG + bn*GN + tx*8;
        float4 o0 = make_float4(acc[i][0]+bsum[0], acc[i][1]+bsum[1],
                                acc[i][2]+bsum[2], acc[i][3]+bsum[3]);
        float4 o1 = make_float4(acc[i][4]+bsum[4], acc[i][5]+bsum[5],
                                acc[i][6]+bsum[6], acc[i][7]+bsum[7]);
        *(float4*)o = o0;
        *(float4*)(o+4) = o1;
    }
}

// K3: LSTM scan over T; one block handles 2 batch elements (independent)
__global__ void __launch_bounds__(512) k_lstm()
{
    __shared__ float hs[2][HD];
    __shared__ float gs[2][HG];
    int tid = threadIdx.x;
    int b0 = blockIdx.x*2;
    if (tid < HD) { hs[0][tid] = 0.f; hs[1][tid] = 0.f; }
    float c0 = 0.f, c1 = 0.f;
    __syncthreads();
    for (int t = 0; t < TT; t++) {
        const float* xg = g_xg + t*(BB*HG);
        float a0 = xg[b0*HG + tid];
        float a1 = xg[(b0+1)*HG + tid];
        const float* w = g_WhhT + tid;
#pragma unroll 4
        for (int k = 0; k < HD; k++) {
            float wv = w[k*HG];
            a0 += wv*hs[0][k];
            a1 += wv*hs[1][k];
        }
        gs[0][tid] = a0; gs[1][tid] = a1;
        __syncthreads();
        if (tid < HD) {
            float i0 = sigmoidf_(gs[0][tid]);
            float f0 = sigmoidf_(gs[0][HD+tid]);
            float g0 = tanhf(gs[0][2*HD+tid]);
            float o0 = sigmoidf_(gs[0][3*HD+tid]);
            c0 = f0*c0 + i0*g0;
            hs[0][tid] = o0*tanhf(c0);
            float i1 = sigmoidf_(gs[1][tid]);
            float f1 = sigmoidf_(gs[1][HD+tid]);
            float g1 = tanhf(gs[1][2*HD+tid]);
            float o1 = sigmoidf_(gs[1][3*HD+tid]);
            c1 = f1*c1 + i1*g1;
            hs[1][tid] = o1*tanhf(c1);
        }
        __syncthreads();
    }
    if (tid < HD) {
        g_hT[b0*HD+tid]     = hs[0][tid];
        g_hT[(b0+1)*HD+tid] = hs[1][tid];
    }
}

// K4: VAE head + fc_in + time-invariant part of gru input gates. One block per b.
__global__ void __launch_bounds__(256) k_head(
    const float* __restrict__ eps,
    const float* __restrict__ muW, const float* __restrict__ mub,
    const float* __restrict__ lvW, const float* __restrict__ lvb,
    const float* __restrict__ fcW, const float* __restrict__ fcb,
    const float* __restrict__ gWih, const float* __restrict__ gbih,
    float* __restrict__ out)
{
    __shared__ float h[HD];
    __shared__ float mu_s[ZD], lv_s[ZD], emb[ZD];
    __shared__ float xs[XD];
    int b = blockIdx.x, tid = threadIdx.x;
    if (tid < HD) h[tid] = g_hT[b*HD+tid];
    __syncthreads();
    if (tid < 2*ZD) {
        int o = tid & 63;
        const float* W = (tid < ZD) ? (muW + o*HD) : (lvW + o*HD);
        float acc = (tid < ZD) ? mub[o] : lvb[o];
        for (int k = 0; k < HD; k++) acc += W[k]*h[k];
        acc = leakyf_(acc, 0.1f);
        if (tid < ZD) mu_s[o] = acc;
        else          lv_s[o] = fminf(10.f, fmaxf(-10.f, acc));
    }
    __syncthreads();
    if (tid < ZD) {
        float m = mu_s[tid], lv = lv_s[tid];
        out[BB*TT*9 + b*ZD + tid] = m;                 // mu output
        out[BB*TT*9 + BB*ZD + b*ZD + tid] = lv;        // logvar output
        emb[tid] = m + eps[b*ZD+tid]*expf(0.5f*lv);
    }
    __syncthreads();
    {
        float acc = fcb[tid];
        const float* W = fcW + tid*ZD;
        for (int k = 0; k < ZD; k++) acc += W[k]*emb[k];
        xs[tid] = acc;
    }
    __syncthreads();
    for (int g = tid; g < GG; g += 256) {
        float acc = gbih[g];
        const float* W = gWih + g*261;
        for (int k = 0; k < XD; k++) acc += W[k]*xs[k];
        g_gxbase[b*GG+g] = acc;
    }
}

// K5: GRU scan + joint-frame head; one block handles 2 batch elements
__global__ void __launch_bounds__(800) k_gru(
    const float* __restrict__ noise_eps,
    const float* __restrict__ gWih, const float* __restrict__ gbhh,
    const float* __restrict__ W1, const float* __restrict__ b1,
    const float* __restrict__ W2, const float* __restrict__ b2,
    float* __restrict__ out)
{
    __shared__ float hs[2][GH];
    __shared__ float gxs[2][GG];
    __shared__ float ghs[2][GG];
    __shared__ float f1s[2][ZD];
    __shared__ float ns[8];
    int tid = threadIdx.x;
    int b0 = blockIdx.x*2;

    for (int j = tid; j < 2*GH; j += 800) (&hs[0][0])[j] = 0.f;

    float wn0=0,wn1=0,wn2=0,wn3=0,wt=0,bh=0,gx0b=0,gx1b=0;
    if (tid < GG) {
        const float* W = gWih + tid*261;
        wn0=W[256]; wn1=W[257]; wn2=W[258]; wn3=W[259]; wt=W[260];
        bh = gbhh[tid];
        gx0b = g_gxbase[b0*GG+tid];
        gx1b = g_gxbase[(b0+1)*GG+tid];
    }
    __syncthreads();
    const float inv = 1.0f/(float)(TT-1);
    for (int t = 0; t < TT; t++) {
        if (tid < 8) {
            int bb = tid >> 2, j = tid & 3;
            ns[tid] = noise_eps[t*(BB*4) + (b0+bb)*4 + j] * 0.1f;
        }
        __syncthreads();
        if (tid < GG) {
            float tv = (float)t * inv;
            float gx0 = gx0b + wn0*ns[0]+wn1*ns[1]+wn2*ns[2]+wn3*ns[3] + wt*tv;
            float gx1 = gx1b + wn0*ns[4]+wn1*ns[5]+wn2*ns[6]+wn3*ns[7] + wt*tv;
            float a0 = bh, a1 = bh;
            const float* w = g_gWhhT + tid;
#pragma unroll 3
            for (int k = 0; k < GH; k++) {
                float wv = w[k*GG];
                a0 += wv*hs[0][k];
                a1 += wv*hs[1][k];
            }
            gxs[0][tid]=gx0; gxs[1][tid]=gx1;
            ghs[0][tid]=a0;  ghs[1][tid]=a1;
        }
        __syncthreads();
        if (tid < 2*GH) {
            int bb = (tid < GH) ? 0 : 1;
            int j  = tid - bb*GH;
            float r = sigmoidf_(gxs[bb][j]      + ghs[bb][j]);
            float z = sigmoidf_(gxs[bb][GH+j]   + ghs[bb][GH+j]);
            float n = tanhf(gxs[bb][2*GH+j] + r*ghs[bb][2*GH+j]);
            hs[bb][j] = (1.f - z)*n + z*hs[bb][j];
        }
        __syncthreads();
        if (tid < 2*ZD) {
            int bb = tid >> 6, o = tid & 63;
            float acc = b1[o];
            const float* W = W1 + o*GH;
            for (int k = 0; k < GH; k++) acc += W[k]*hs[bb][k];
            f1s[bb][o] = leakyf_(acc, 0.2f);
        }
        __syncthreads();
        if (tid < 18) {
            int bb = tid / 9, i = tid - bb*9;
            float acc = b2[i];
            const float* W = W2 + i*ZD;
            for (int o = 0; o < ZD; o++) acc += W[o]*f1s[bb][o];
            out[(b0+bb)*(TT*9) + t*9 + i] = sigmoidf_(acc);
        }
        // next-iteration sync at loop top guards f1s/ns reuse
    }
}

extern "C" void kernel_launch(void* const* d_in, const int* in_sizes, int n_in,
                              void* d_out, int out_size)
{
    const float* input_data = (const float*)d_in[0];
    const float* eps        = (const float*)d_in[1];
    const float* noise_eps  = (const float*)d_in[2];
    const float* proj_W     = (const float*)d_in[3];
    const float* proj_b     = (const float*)d_in[4];
    const float* lstm_Wih   = (const float*)d_in[5];
    const float* lstm_Whh   = (const float*)d_in[6];
    const float* lstm_bih   = (const float*)d_in[7];
    const float* lstm_bhh   = (const float*)d_in[8];
    const float* mu_W       = (const float*)d_in[9];
    const float* mu_b       = (const float*)d_in[10];
    const float* lv_W       = (const float*)d_in[11];
    const float* lv_b       = (const float*)d_in[12];
    const float* fcin_W     = (const float*)d_in[13];
    const float* fcin_b     = (const float*)d_in[14];
    const float* gru_Wih    = (const float*)d_in[15];
    const float* gru_Whh    = (const float*)d_in[16];
    const float* gru_bih    = (const float*)d_in[17];
    const float* gru_bhh    = (const float*)d_in[18];
    const float* jf_W1      = (const float*)d_in[19];
    const float* jf_b1      = (const float*)d_in[20];
    const float* jf_W2      = (const float*)d_in[21];
    const float* jf_b2      = (const float*)d_in[22];
    float* out = (float*)d_out;

    k_prep<<<64, 256>>>(lstm_Whh, gru_Whh);
    k_proj<<<BB*TT, 512>>>(input_data, proj_W, proj_b);
    dim3 g2(TT*BB/GM, HG/GN);   // (100, 4)
    k_gemm<<<g2, 256>>>(lstm_Wih, lstm_bih, lstm_bhh);
    k_lstm<<<BB/2, 512>>>();
    k_head<<<BB, 256>>>(eps, mu_W, mu_b, lv_W, lv_b, fcin_W, fcin_b,
                        gru_Wih, gru_bih, out);
    k_gru<<<BB/2, 800>>>(noise_eps, gru_Wih, gru_bhh, jf_W1, jf_b1, jf_W2, jf_b2, out);
}

// round 3
// speedup vs baseline: 2.3380x; 2.3380x over previous
#include <cuda_runtime.h>
#include <math.h>

#define BB 128
#define TT 100
#define PD 4096
#define HG 512
#define HD 128
#define GH 261
#define GG 783
#define ZD 64
#define XD 256

__device__ float g_proj[BB*TT*PD];
__device__ float g_Wih32[HG*PD];
__device__ float g_xg[TT*BB*HG];
__device__ float4 g_gWhh4[41*GG];   // gru Whh k=96..259: [p][g]
__device__ float4 g_W1T4[66*ZD];    // jf_W1 packs (zero-padded past 261)
__device__ float g_hT[BB*HD];
__device__ float g_gxbase[BB*GG];

__device__ __forceinline__ float sigmoidf_(float x){ return 1.0f/(1.0f+expf(-x)); }
__device__ __forceinline__ float leakyf_(float x, float s){ return x >= 0.0f ? x : s*x; }
__device__ __forceinline__ void fma2(unsigned long long& a, unsigned long long w, unsigned long long h){
    asm("fma.rn.f32x2 %0, %1, %2, %0;" : "+l"(a) : "l"(w), "l"(h));
}
__device__ __forceinline__ void cp16(void* s, const void* g){
    unsigned ss = (unsigned)__cvta_generic_to_shared(s);
    asm volatile("cp.async.cg.shared.global [%0], [%1], 16;\n" :: "r"(ss), "l"(g));
}
#define MMA_TF32(c, au, bu) \
  asm volatile("mma.sync.aligned.m16n8k8.row.col.f32.tf32.tf32.f32 " \
    "{%0,%1,%2,%3},{%4,%5,%6,%7},{%8,%9},{%0,%1,%2,%3};\n" \
    : "+f"(c[0]),"+f"(c[1]),"+f"(c[2]),"+f"(c[3]) \
    : "r"(au[0]),"r"(au[1]),"r"(au[2]),"r"(au[3]),"r"(bu[0]),"r"(bu[1]))

// K0: tf32 copy of lstm_Wih, float4 packs for gru Whh tail and jf_W1
__global__ void k_prep(const float* __restrict__ Wih,
                       const float* __restrict__ gWhh,
                       const float* __restrict__ W1)
{
    int i0 = blockIdx.x*blockDim.x + threadIdx.x;
    int st = gridDim.x*blockDim.x;
    for (int i = i0; i < HG*PD; i += st){
        unsigned u; asm("cvt.rna.tf32.f32 %0, %1;" : "=r"(u) : "f"(Wih[i]));
        g_Wih32[i] = __uint_as_float(u);
    }
    for (int i = i0; i < 41*GG; i += st){
        int p = i / GG, g = i - p*GG;
        const float* r = gWhh + (size_t)g*GH + 96 + 4*p;
        g_gWhh4[i] = make_float4(r[0], r[1], r[2], r[3]);
    }
    for (int i = i0; i < 66*ZD; i += st){
        int p = i >> 6, o = i & 63;
        const float* r = W1 + (size_t)o*GH;
        int k = 4*p;
        float4 v;
        v.x = (k   < GH) ? r[k]   : 0.f;
        v.y = (k+1 < GH) ? r[k+1] : 0.f;
        v.z = (k+2 < GH) ? r[k+2] : 0.f;
        v.w = (k+3 < GH) ? r[k+3] : 0.f;
        g_W1T4[i] = v;
    }
}

// K1: proj = tf32(leaky(pose @ proj_W^T + b)), 8 rows per block
__global__ void __launch_bounds__(512) k_proj(const float* __restrict__ pose,
                                              const float* __restrict__ W,
                                              const float* __restrict__ bias)
{
    __shared__ float p[8][9];
    int r0 = blockIdx.x*8;
    int tid = threadIdx.x;
    if (tid < 72) p[tid/9][tid%9] = pose[r0*9 + tid];
    __syncthreads();
#pragma unroll
    for (int i = 0; i < 8; i++){
        int k = tid + i*512;
        const float* w = W + k*9;
        float wv[9];
#pragma unroll
        for (int j = 0; j < 9; j++) wv[j] = w[j];
        float bk = bias[k];
#pragma unroll
        for (int r = 0; r < 8; r++){
            float acc = bk;
#pragma unroll
            for (int j = 0; j < 9; j++) acc += wv[j]*p[r][j];
            acc = leakyf_(acc, 0.1f);
            unsigned u; asm("cvt.rna.tf32.f32 %0, %1;" : "=r"(u) : "f"(acc));
            g_proj[(size_t)(r0+r)*PD + k] = __uint_as_float(u);
        }
    }
}

// K2: tf32 tensor-core GEMM  x_gates = proj @ Wih^T + bih + bhh  -> (t,b,g)
#define SMS 36
__global__ void __launch_bounds__(256) k_gemm(const float* __restrict__ bih,
                                              const float* __restrict__ bhh)
{
    extern __shared__ float sm[];
    float* As = sm;                 // [2][128][SMS]
    float* Bs = sm + 2*128*SMS;
    int tid = threadIdx.x;
    int bm = blockIdx.x, bn = blockIdx.y;
    const float* Ag = g_proj  + (size_t)bm*128*PD;
    const float* Bg = g_Wih32 + (size_t)bn*128*PD;
    int lane = tid & 31, warp = tid >> 5;
    int wm = warp >> 2, wn = warp & 3;
    float acc[4][4][4];
#pragma unroll
    for (int a = 0; a < 4; a++)
#pragma unroll
        for (int b = 0; b < 4; b++)
#pragma unroll
            for (int c = 0; c < 4; c++) acc[a][b][c] = 0.f;

    for (int i = 0; i < 4; i++){
        int idx = tid + i*256, row = idx >> 3, f4 = idx & 7;
        cp16(As + row*SMS + f4*4, Ag + (size_t)row*PD + f4*4);
        cp16(Bs + row*SMS + f4*4, Bg + (size_t)row*PD + f4*4);
    }
    asm volatile("cp.async.commit_group;\n");
    for (int kt = 0; kt < PD/32; kt++){
        int buf = kt & 1;
        if (kt+1 < PD/32){
            int nb = buf^1;
            for (int i = 0; i < 4; i++){
                int idx = tid + i*256, row = idx >> 3, f4 = idx & 7;
                cp16(As + nb*128*SMS + row*SMS + f4*4, Ag + (size_t)row*PD + (kt+1)*32 + f4*4);
                cp16(Bs + nb*128*SMS + row*SMS + f4*4, Bg + (size_t)row*PD + (kt+1)*32 + f4*4);
            }
        }
        asm volatile("cp.async.commit_group;\n");
        asm volatile("cp.async.wait_group 1;\n");
        __syncthreads();
        const float* A = As + buf*128*SMS;
        const float* B = Bs + buf*128*SMS;
#pragma unroll
        for (int kk = 0; kk < 4; kk++){
            int kb = kk*8 + (lane & 3);
            unsigned au[4][4], bu[4][2];
#pragma unroll
            for (int mt = 0; mt < 4; mt++){
                const float* ap = A + (wm*64 + mt*16 + (lane>>2))*SMS + kb;
                au[mt][0] = __float_as_uint(ap[0]);
                au[mt][1] = __float_as_uint(ap[8*SMS]);
                au[mt][2] = __float_as_uint(ap[4]);
                au[mt][3] = __float_as_uint(ap[8*SMS+4]);
            }
#pragma unroll
            for (int nt = 0; nt < 4; nt++){
                const float* bp = B + (wn*32 + nt*8 + (lane>>2))*SMS + kb;
                bu[nt][0] = __float_as_uint(bp[0]);
                bu[nt][1] = __float_as_uint(bp[4]);
            }
#pragma unroll
            for (int mt = 0; mt < 4; mt++)
#pragma unroll
                for (int nt = 0; nt < 4; nt++)
                    MMA_TF32(acc[mt][nt], au[mt], bu[nt]);
        }
        __syncthreads();
    }
#pragma unroll
    for (int mt = 0; mt < 4; mt++){
#pragma unroll
        for (int nt = 0; nt < 4; nt++){
            int col = bn*128 + wn*32 + nt*8 + (lane&3)*2;
            float bs0 = bih[col]   + bhh[col];
            float bs1 = bih[col+1] + bhh[col+1];
            int r0 = bm*128 + wm*64 + mt*16 + (lane>>2);
            int b0i = r0/TT, t0 = r0 - b0i*TT;
            *(float2*)(g_xg + (size_t)t0*(BB*HG) + b0i*HG + col) =
                make_float2(acc[mt][nt][0]+bs0, acc[mt][nt][1]+bs1);
            int r1 = r0 + 8;
            int b1i = r1/TT, t1 = r1 - b1i*TT;
            *(float2*)(g_xg + (size_t)t1*(BB*HG) + b1i*HG + col) =
                make_float2(acc[mt][nt][2]+bs0, acc[mt][nt][3]+bs1);
        }
    }
}

// K3: LSTM scan, 1 batch/block, weights in regs+smem, packed f32x2 FMAs
__global__ void __launch_bounds__(512) k_lstm(const float* __restrict__ Whh)
{
    extern __shared__ float sm[];
    unsigned long long* wsu = (unsigned long long*)sm;  // [32][512]
    float* hs = sm + 32*512*2;
    float* gs = hs + 128;
    int tid = threadIdx.x, b = blockIdx.x;

    const ulonglong2* wrow = (const ulonglong2*)(Whh + (size_t)tid*HD);
    unsigned long long wr2[32];
#pragma unroll
    for (int i = 0; i < 16; i++){
        ulonglong2 v = wrow[i];
        wr2[2*i] = v.x; wr2[2*i+1] = v.y;
    }
#pragma unroll
    for (int i = 0; i < 16; i++){
        ulonglong2 v = wrow[16+i];
        wsu[(2*i)*512 + tid]   = v.x;
        wsu[(2*i+1)*512 + tid] = v.y;
    }
    if (tid < HD) hs[tid] = 0.f;
    float c = 0.f;
    __syncthreads();
    const float* xg = g_xg + b*HG + tid;
    float xcur = xg[0];
    for (int t = 0; t < TT; t++){
        float xnext = (t < TT-1) ? xg[(size_t)(t+1)*(BB*HG)] : 0.f;
        const unsigned long long* H = (const unsigned long long*)hs;
        unsigned long long a2 = 0ull, b2 = 0ull;
#pragma unroll
        for (int i = 0; i < 32; i++) fma2(a2, wr2[i], H[i]);
#pragma unroll
        for (int i = 0; i < 32; i++) fma2(b2, wsu[i*512 + tid], H[32+i]);
        float a0,a1,b0,b1;
        asm("mov.b64 {%0,%1}, %2;" : "=f"(a0), "=f"(a1) : "l"(a2));
        asm("mov.b64 {%0,%1}, %2;" : "=f"(b0), "=f"(b1) : "l"(b2));
        gs[tid] = xcur + (a0+a1) + (b0+b1);
        __syncthreads();
        if (tid < HD){
            float ii = sigmoidf_(gs[tid]);
            float ff = sigmoidf_(gs[HD+tid]);
            float gg = tanhf(gs[2*HD+tid]);
            float oo = sigmoidf_(gs[3*HD+tid]);
            c = ff*c + ii*gg;
            hs[tid] = oo*tanhf(c);
        }
        __syncthreads();
        xcur = xnext;
    }
    if (tid < HD) g_hT[b*HD + tid] = hs[tid];
}

// K4: VAE head + fc_in + static GRU input gates
__global__ void __launch_bounds__(256) k_head(
    const float* __restrict__ eps,
    const float* __restrict__ muW, const float* __restrict__ mub,
    const float* __restrict__ lvW, const float* __restrict__ lvb,
    const float* __restrict__ fcW, const float* __restrict__ fcb,
    const float* __restrict__ gWih, const float* __restrict__ gbih,
    float* __restrict__ out)
{
    __shared__ float h[HD];
    __shared__ float mu_s[ZD], lv_s[ZD], emb[ZD];
    __shared__ float xs[XD];
    int b = blockIdx.x, tid = threadIdx.x;
    if (tid < HD) h[tid] = g_hT[b*HD+tid];
    __syncthreads();
    if (tid < 2*ZD) {
        int o = tid & 63;
        const float* W = (tid < ZD) ? (muW + o*HD) : (lvW + o*HD);
        float acc = (tid < ZD) ? mub[o] : lvb[o];
        for (int k = 0; k < HD; k++) acc += W[k]*h[k];
        acc = leakyf_(acc, 0.1f);
        if (tid < ZD) mu_s[o] = acc;
        else          lv_s[o] = fminf(10.f, fmaxf(-10.f, acc));
    }
    __syncthreads();
    if (tid < ZD) {
        float m = mu_s[tid], lv = lv_s[tid];
        out[BB*TT*9 + b*ZD + tid] = m;
        out[BB*TT*9 + BB*ZD + b*ZD + tid] = lv;
        emb[tid] = m + eps[b*ZD+tid]*expf(0.5f*lv);
    }
    __syncthreads();
    {
        float acc = fcb[tid];
        const float* W = fcW + tid*ZD;
        for (int k = 0; k < ZD; k++) acc += W[k]*emb[k];
        xs[tid] = acc;
    }
    __syncthreads();
    for (int g = tid; g < GG; g += 256) {
        float acc = gbih[g];
        const float* W = gWih + (size_t)g*GH;
        for (int k = 0; k < XD; k++) acc += W[k]*xs[k];
        g_gxbase[b*GG+g] = acc;
    }
}

// K5: GRU scan + joint-frame head, 2 batches/block, hybrid weights + f32x2
__global__ void __launch_bounds__(800) k_gru(
    const float* __restrict__ noise_eps,
    const float* __restrict__ gWih, const float* __restrict__ gWhh,
    const float* __restrict__ gbhh,
    const float* __restrict__ b1,
    const float* __restrict__ W2, const float* __restrict__ b2,
    float* __restrict__ out)
{
    extern __shared__ float sm[];
    float* wsp_f = sm;                   // [32][784] pairs (float2) k=32..95
    float* hb0  = sm + 32*784*2;         // 264 (pad zero)
    float* hb1  = hb0 + 264;
    float* sums = hb1 + 264;             // [2][784]
    float* ghn  = sums + 2*784;          // [2][264]
    float* f1s  = ghn + 2*264;           // [2][64]
    float* ns   = f1s + 128;             // 8
    int tid = threadIdx.x;
    int b0 = blockIdx.x*2;

    for (int j = tid; j < 528; j += 800) hb0[j] = 0.f;

    unsigned long long wr2[16];
    float w260=0,wn0=0,wn1=0,wn2=0,wn3=0,wt=0,bh=0,gx0b=0,gx1b=0;
    if (tid < GG){
        const float* row = gWhh + (size_t)tid*GH;
#pragma unroll
        for (int i = 0; i < 16; i++)
            asm("mov.b64 %0, {%1,%2};" : "=l"(wr2[i]) : "f"(row[2*i]), "f"(row[2*i+1]));
        float2* wsp2 = (float2*)wsp_f;
#pragma unroll
        for (int i = 0; i < 32; i++)
            wsp2[i*784 + tid] = make_float2(row[32+2*i], row[33+2*i]);
        w260 = row[260];
        const float* Wi = gWih + (size_t)tid*GH;
        wn0=Wi[256]; wn1=Wi[257]; wn2=Wi[258]; wn3=Wi[259]; wt=Wi[260];
        bh = gbhh[tid];
        gx0b = g_gxbase[b0*GG + tid];
        gx1b = g_gxbase[(b0+1)*GG + tid];
    }
    __syncthreads();
    const float inv = 1.0f/(float)(TT-1);
    for (int t = 0; t < TT; t++){
        if (tid < 8){
            int bb = tid >> 2, j = tid & 3;
            ns[tid] = noise_eps[t*(BB*4) + (b0+bb)*4 + j] * 0.1f;
        }
        __syncthreads();
        if (tid < GG){
            float tv = (float)t * inv;
            float gx0 = gx0b + wn0*ns[0]+wn1*ns[1]+wn2*ns[2]+wn3*ns[3] + wt*tv;
            float gx1 = gx1b + wn0*ns[4]+wn1*ns[5]+wn2*ns[6]+wn3*ns[7] + wt*tv;
            unsigned long long a0p = 0ull, a1p = 0ull;
            const unsigned long long* H0 = (const unsigned long long*)hb0;
            const unsigned long long* H1 = (const unsigned long long*)hb1;
#pragma unroll
            for (int i = 0; i < 16; i++){
                fma2(a0p, wr2[i], H0[i]);
                fma2(a1p, wr2[i], H1[i]);
            }
            const unsigned long long* ws = (const unsigned long long*)wsp_f;
#pragma unroll
            for (int i = 0; i < 32; i++){
                unsigned long long w = ws[i*784 + tid];
                fma2(a0p, w, H0[16+i]);
                fma2(a1p, w, H1[16+i]);
            }
            const ulonglong2* wp = (const ulonglong2*)g_gWhh4 + tid;
#pragma unroll 8
            for (int p = 0; p < 41; p++){
                ulonglong2 w = wp[(size_t)p*GG];
                fma2(a0p, w.x, H0[48+2*p]);  fma2(a1p, w.x, H1[48+2*p]);
                fma2(a0p, w.y, H0[49+2*p]);  fma2(a1p, w.y, H1[49+2*p]);
            }
            float s00,s01,s10,s11;
            asm("mov.b64 {%0,%1}, %2;" : "=f"(s00), "=f"(s01) : "l"(a0p));
            asm("mov.b64 {%0,%1}, %2;" : "=f"(s10), "=f"(s11) : "l"(a1p));
            float gh0 = bh + (s00+s01) + w260*hb0[260];
            float gh1 = bh + (s10+s11) + w260*hb1[260];
            float v0 = gx0 + gh0, v1 = gx1 + gh1;
            if (tid >= 522){
                v0 = gx0; v1 = gx1;
                ghn[tid-522] = gh0; ghn[264 + tid-522] = gh1;
            }
            sums[tid] = v0; sums[784 + tid] = v1;
        }
        __syncthreads();
        if (tid < 522){
            int bb = tid/261, j = tid - bb*261;
            float* hb = bb ? hb1 : hb0;
            const float* s = sums + bb*784;
            float r = sigmoidf_(s[j]);
            float z = sigmoidf_(s[261+j]);
            float n = tanhf(s[522+j] + r*ghn[bb*264 + j]);
            hb[j] = (1.f - z)*n + z*hb[j];
        }
        __syncthreads();
        if (tid < 128){
            int bb = tid >> 6, o = tid & 63;
            const float4* hv = (const float4*)(bb ? hb1 : hb0);
            const float4* Wv = g_W1T4 + o;
            float acc = b1[o];
#pragma unroll
            for (int p = 0; p < 66; p++){
                float4 w = Wv[p*ZD];
                float4 h = hv[p];
                acc += w.x*h.x + w.y*h.y + w.z*h.z + w.w*h.w;
            }
            f1s[bb*64 + o] = leakyf_(acc, 0.2f);
        }
        __syncthreads();
        if (tid < 18){
            int bb = tid/9, i = tid - bb*9;
            float acc = b2[i];
            const float* W = W2 + i*ZD;
            for (int o = 0; o < ZD; o++) acc += W[o]*f1s[bb*64 + o];
            out[(size_t)(b0+bb)*(TT*9) + t*9 + i] = sigmoidf_(acc);
        }
        __syncthreads();
    }
}

extern "C" void kernel_launch(void* const* d_in, const int* in_sizes, int n_in,
                              void* d_out, int out_size)
{
    const float* input_data = (const float*)d_in[0];
    const float* eps        = (const float*)d_in[1];
    const float* noise_eps  = (const float*)d_in[2];
    const float* proj_W     = (const float*)d_in[3];
    const float* proj_b     = (const float*)d_in[4];
    const float* lstm_Wih   = (const float*)d_in[5];
    const float* lstm_Whh   = (const float*)d_in[6];
    const float* lstm_bih   = (const float*)d_in[7];
    const float* lstm_bhh   = (const float*)d_in[8];
    const float* mu_W       = (const float*)d_in[9];
    const float* mu_b       = (const float*)d_in[10];
    const float* lv_W       = (const float*)d_in[11];
    const float* lv_b       = (const float*)d_in[12];
    const float* fcin_W     = (const float*)d_in[13];
    const float* fcin_b     = (const float*)d_in[14];
    const float* gru_Wih    = (const float*)d_in[15];
    const float* gru_Whh    = (const float*)d_in[16];
    const float* gru_bih    = (const float*)d_in[17];
    const float* gru_bhh    = (const float*)d_in[18];
    const float* jf_W1      = (const float*)d_in[19];
    const float* jf_b1      = (const float*)d_in[20];
    const float* jf_W2      = (const float*)d_in[21];
    const float* jf_b2      = (const float*)d_in[22];
    float* out = (float*)d_out;

    static int done = 0;
    if (!done){
        cudaFuncSetAttribute(k_gemm, cudaFuncAttributeMaxDynamicSharedMemorySize, 2*2*128*SMS*4);
        cudaFuncSetAttribute(k_lstm, cudaFuncAttributeMaxDynamicSharedMemorySize, 32*512*8 + (128+512)*4);
        cudaFuncSetAttribute(k_gru,  cudaFuncAttributeMaxDynamicSharedMemorySize,
                             (32*784*2 + 528 + 2*784 + 2*264 + 128 + 8)*4);
        done = 1;
    }

    k_prep<<<160, 256>>>(lstm_Wih, gru_Whh, jf_W1);
    k_proj<<<BB*TT/8, 512>>>(input_data, proj_W, proj_b);
    dim3 g2(TT*BB/128, HG/128);
    k_gemm<<<g2, 256, 2*2*128*SMS*4>>>(lstm_bih, lstm_bhh);
    k_lstm<<<BB, 512, 32*512*8 + (128+512)*4>>>(lstm_Whh);
    k_head<<<BB, 256>>>(eps, mu_W, mu_b, lv_W, lv_b, fcin_W, fcin_b,
                        gru_Wih, gru_bih, out);
    k_gru<<<BB/2, 800, (32*784*2 + 528 + 2*784 + 2*264 + 128 + 8)*4>>>(
        noise_eps, gru_Wih, gru_Whh, gru_bhh, jf_b1, jf_W2, jf_b2, out);
}

// round 5
// speedup vs baseline: 3.5352x; 1.5121x over previous
#include <cuda_runtime.h>
#include <cuda_fp16.h>
#include <math.h>
#include <stdint.h>

#define BB 128
#define TT 100
#define PD 4096
#define HG 512
#define HD 128
#define GH 261
#define GG 783
#define ZD 64
#define XD 256

__device__ __half g_projh[BB*TT*PD];   // fp16 activations (b*T+t, 4096)
__device__ __half g_Wih16[HG*PD];      // fp16 lstm_Wih
__device__ float g_xg[TT*BB*HG];       // (t,b,512)
__device__ float4 g_gWhh4[41*GG];      // gru Whh k=96..259: [p][g]
__device__ float4 g_W1T4[66*ZD];       // jf_W1 packs (zero-padded past 261)
__device__ float g_hT[BB*HD];
__device__ float g_gxbase[BB*GG];

__device__ __forceinline__ float sigmoidf_(float x){ return 1.0f/(1.0f+expf(-x)); }
__device__ __forceinline__ float leakyf_(float x, float s){ return x >= 0.0f ? x : s*x; }
__device__ __forceinline__ void fma2(unsigned long long& a, unsigned long long w, unsigned long long h){
    asm("fma.rn.f32x2 %0, %1, %2, %0;" : "+l"(a) : "l"(w), "l"(h));
}
__device__ __forceinline__ void cp16(void* s, const void* g){
    unsigned ss = (unsigned)__cvta_generic_to_shared(s);
    asm volatile("cp.async.cg.shared.global [%0], [%1], 16;\n" :: "r"(ss), "l"(g));
}
#define MMA_F16(c, au, bu) \
  asm volatile("mma.sync.aligned.m16n8k16.row.col.f32.f16.f16.f32 " \
    "{%0,%1,%2,%3},{%4,%5,%6,%7},{%8,%9},{%0,%1,%2,%3};\n" \
    : "+f"(c[0]),"+f"(c[1]),"+f"(c[2]),"+f"(c[3]) \
    : "r"(au[0]),"r"(au[1]),"r"(au[2]),"r"(au[3]),"r"(bu[0]),"r"(bu[1]))

// K0: fp16 copy of lstm_Wih + float4 packs for gru Whh tail and jf_W1
__global__ void k_prep(const float* __restrict__ Wih,
                       const float* __restrict__ gWhh,
                       const float* __restrict__ W1)
{
    int i0 = blockIdx.x*blockDim.x + threadIdx.x;
    int st = gridDim.x*blockDim.x;
    for (int i = i0; i < HG*PD; i += st)
        g_Wih16[i] = __float2half_rn(Wih[i]);
    for (int i = i0; i < 41*GG; i += st){
        int p = i / GG, g = i - p*GG;
        const float* r = gWhh + (size_t)g*GH + 96 + 4*p;
        g_gWhh4[i] = make_float4(r[0], r[1], r[2], r[3]);
    }
    for (int i = i0; i < 66*ZD; i += st){
        int p = i >> 6, o = i & 63;
        const float* r = W1 + (size_t)o*GH;
        int k = 4*p;
        float4 v;
        v.x = (k   < GH) ? r[k]   : 0.f;
        v.y = (k+1 < GH) ? r[k+1] : 0.f;
        v.z = (k+2 < GH) ? r[k+2] : 0.f;
        v.w = (k+3 < GH) ? r[k+3] : 0.f;
        g_W1T4[i] = v;
    }
}

// K1: proj = fp16(leaky(pose @ proj_W^T + b)), 8 rows per block
__global__ void __launch_bounds__(512) k_proj(const float* __restrict__ pose,
                                              const float* __restrict__ W,
                                              const float* __restrict__ bias)
{
    __shared__ float p[8][9];
    int r0 = blockIdx.x*8;
    int tid = threadIdx.x;
    if (tid < 72) p[tid/9][tid%9] = pose[r0*9 + tid];
    __syncthreads();
#pragma unroll
    for (int i = 0; i < 8; i++){
        int k = tid + i*512;
        const float* w = W + k*9;
        float wv[9];
#pragma unroll
        for (int j = 0; j < 9; j++) wv[j] = w[j];
        float bk = bias[k];
#pragma unroll
        for (int r = 0; r < 8; r++){
            float acc = bk;
#pragma unroll
            for (int j = 0; j < 9; j++) acc += wv[j]*p[r][j];
            g_projh[(size_t)(r0+r)*PD + k] = __float2half_rn(leakyf_(acc, 0.1f));
        }
    }
}

// K2: fp16 mma.sync GEMM: x_gates = proj @ Wih^T + bih + bhh -> (t,b,g)
// 128x128 tiles, K-chunk 64, double-buffered cp.async, 8 warps.
#define SMSH 72   // halves per smem row (36 words), conflict-free
#define KC 64
__global__ void __launch_bounds__(256, 2) k_gemm(const float* __restrict__ bih,
                                                 const float* __restrict__ bhh)
{
    extern __shared__ __align__(16) char smc[];
    __half* Ash = (__half*)smc;                       // [2][128][72]
    __half* Bsh = (__half*)(smc + 2*128*SMSH*2);      // [2][128][72]
    int tid = threadIdx.x, lane = tid & 31, warp = tid >> 5;
    int bn = blockIdx.x, bm = blockIdx.y;
    const __half* Ag = g_projh + (size_t)bm*128*PD;
    const __half* Bg = g_Wih16 + (size_t)bn*128*PD;
    int wm = warp >> 2, wn = warp & 3;
    float acc[4][4][4];
#pragma unroll
    for (int a = 0; a < 4; a++)
#pragma unroll
        for (int b = 0; b < 4; b++)
#pragma unroll
            for (int c = 0; c < 4; c++) acc[a][b][c] = 0.f;

    // chunk 0
    for (int i = tid; i < 1024; i += 256){
        int row = i >> 3, sub = i & 7;
        cp16(Ash + row*SMSH + sub*8, Ag + (size_t)row*PD + sub*8);
    }
    for (int i = tid; i < 1024; i += 256){
        int row = i >> 3, sub = i & 7;
        cp16(Bsh + row*SMSH + sub*8, Bg + (size_t)row*PD + sub*8);
    }
    asm volatile("cp.async.commit_group;\n");

    for (int c = 0; c < PD/KC; c++){
        int buf = c & 1;
        if (c+1 < PD/KC){
            int nb = buf^1;
            int kof = (c+1)*KC;
            for (int i = tid; i < 1024; i += 256){
                int row = i >> 3, sub = i & 7;
                cp16(Ash + nb*128*SMSH + row*SMSH + sub*8, Ag + (size_t)row*PD + kof + sub*8);
            }
            for (int i = tid; i < 1024; i += 256){
                int row = i >> 3, sub = i & 7;
                cp16(Bsh + nb*128*SMSH + row*SMSH + sub*8, Bg + (size_t)row*PD + kof + sub*8);
            }
        }
        asm volatile("cp.async.commit_group;\n");
        asm volatile("cp.async.wait_group 1;\n");
        __syncthreads();
        const uint32_t* A = (const uint32_t*)(Ash + buf*128*SMSH);
        const uint32_t* B = (const uint32_t*)(Bsh + buf*128*SMSH);
#pragma unroll
        for (int kk = 0; kk < 4; kk++){
            int kw = kk*8 + (lane & 3);
            uint32_t au[4][4], bu[4][2];
#pragma unroll
            for (int mt = 0; mt < 4; mt++){
                int r = wm*64 + mt*16 + (lane>>2);
                au[mt][0] = A[r*36 + kw];
                au[mt][1] = A[(r+8)*36 + kw];
                au[mt][2] = A[r*36 + kw + 4];
                au[mt][3] = A[(r+8)*36 + kw + 4];
            }
#pragma unroll
            for (int nt = 0; nt < 4; nt++){
                int n = wn*32 + nt*8 + (lane>>2);
                bu[nt][0] = B[n*36 + kw];
                bu[nt][1] = B[n*36 + kw + 4];
            }
#pragma unroll
            for (int mt = 0; mt < 4; mt++)
#pragma unroll
                for (int nt = 0; nt < 4; nt++)
                    MMA_F16(acc[mt][nt], au[mt], bu[nt]);
        }
        __syncthreads();
    }
#pragma unroll
    for (int mt = 0; mt < 4; mt++){
#pragma unroll
        for (int nt = 0; nt < 4; nt++){
            int col = bn*128 + wn*32 + nt*8 + (lane&3)*2;
            float bs0 = bih[col]   + bhh[col];
            float bs1 = bih[col+1] + bhh[col+1];
            int r0 = bm*128 + wm*64 + mt*16 + (lane>>2);
            int b0i = r0/TT, t0 = r0 - b0i*TT;
            *(float2*)(g_xg + (size_t)t0*(BB*HG) + b0i*HG + col) =
                make_float2(acc[mt][nt][0]+bs0, acc[mt][nt][1]+bs1);
            int r1 = r0 + 8;
            int b1i = r1/TT, t1 = r1 - b1i*TT;
            *(float2*)(g_xg + (size_t)t1*(BB*HG) + b1i*HG + col) =
                make_float2(acc[mt][nt][2]+bs0, acc[mt][nt][3]+bs1);
        }
    }
}

// K3: LSTM scan, 1 batch/block, weights regs+smem, 4 f32x2 accumulators
__global__ void __launch_bounds__(512) k_lstm(const float* __restrict__ Whh)
{
    extern __shared__ float sm[];
    ulonglong2* wsu2 = (ulonglong2*)sm;          // [16][512]: k=64..127
    float* hs = sm + 32768;                      // 128
    float* gs = hs + 128;                        // 512
    int tid = threadIdx.x, b = blockIdx.x;

    const ulonglong2* wrow = (const ulonglong2*)(Whh + (size_t)tid*HD);
    unsigned long long wr2[32];
#pragma unroll
    for (int i = 0; i < 16; i++){
        ulonglong2 v = wrow[i];
        wr2[2*i] = v.x; wr2[2*i+1] = v.y;
    }
#pragma unroll
    for (int i = 0; i < 16; i++) wsu2[i*512 + tid] = wrow[16+i];
    if (tid < HD) hs[tid] = 0.f;
    float c = 0.f;
    __syncthreads();
    const float* xg = g_xg + b*HG + tid;
    float xcur = xg[0];
    for (int t = 0; t < TT; t++){
        float xnext = (t < TT-1) ? xg[(size_t)(t+1)*(BB*HG)] : 0.f;
        const ulonglong2* H2 = (const ulonglong2*)hs;
        unsigned long long a2 = 0ull, c2 = 0ull, d2 = 0ull, e2 = 0ull;
#pragma unroll
        for (int i = 0; i < 8; i++){
            ulonglong2 h0 = H2[2*i], h1 = H2[2*i+1];
            fma2(a2, wr2[4*i],   h0.x);
            fma2(c2, wr2[4*i+1], h0.y);
            fma2(d2, wr2[4*i+2], h1.x);
            fma2(e2, wr2[4*i+3], h1.y);
        }
#pragma unroll
        for (int i = 0; i < 8; i++){
            ulonglong2 w0 = wsu2[(2*i)*512 + tid];
            ulonglong2 w1 = wsu2[(2*i+1)*512 + tid];
            ulonglong2 h0 = H2[16+2*i], h1 = H2[17+2*i];
            fma2(a2, w0.x, h0.x);
            fma2(c2, w0.y, h0.y);
            fma2(d2, w1.x, h1.x);
            fma2(e2, w1.y, h1.y);
        }
        float a0,a1,b0,b1,d0,d1,e0,e1;
        asm("mov.b64 {%0,%1}, %2;" : "=f"(a0), "=f"(a1) : "l"(a2));
        asm("mov.b64 {%0,%1}, %2;" : "=f"(b0), "=f"(b1) : "l"(c2));
        asm("mov.b64 {%0,%1}, %2;" : "=f"(d0), "=f"(d1) : "l"(d2));
        asm("mov.b64 {%0,%1}, %2;" : "=f"(e0), "=f"(e1) : "l"(e2));
        gs[tid] = xcur + ((a0+a1) + (b0+b1)) + ((d0+d1) + (e0+e1));
        __syncthreads();
        if (tid < HD){
            float ii = sigmoidf_(gs[tid]);
            float ff = sigmoidf_(gs[HD+tid]);
            float gg = tanhf(gs[2*HD+tid]);
            float oo = sigmoidf_(gs[3*HD+tid]);
            c = ff*c + ii*gg;
            hs[tid] = oo*tanhf(c);
        }
        __syncthreads();
        xcur = xnext;
    }
    if (tid < HD) g_hT[b*HD + tid] = hs[tid];
}

// K4: VAE head + fc_in + static GRU input gates
__global__ void __launch_bounds__(256) k_head(
    const float* __restrict__ eps,
    const float* __restrict__ muW, const float* __restrict__ mub,
    const float* __restrict__ lvW, const float* __restrict__ lvb,
    const float* __restrict__ fcW, const float* __restrict__ fcb,
    const float* __restrict__ gWih, const float* __restrict__ gbih,
    float* __restrict__ out)
{
    __shared__ float h[HD];
    __shared__ float mu_s[ZD], lv_s[ZD], emb[ZD];
    __shared__ float xs[XD];
    int b = blockIdx.x, tid = threadIdx.x;
    if (tid < HD) h[tid] = g_hT[b*HD+tid];
    __syncthreads();
    if (tid < 2*ZD) {
        int o = tid & 63;
        const float* W = (tid < ZD) ? (muW + o*HD) : (lvW + o*HD);
        float acc = (tid < ZD) ? mub[o] : lvb[o];
        for (int k = 0; k < HD; k++) acc += W[k]*h[k];
        acc = leakyf_(acc, 0.1f);
        if (tid < ZD) mu_s[o] = acc;
        else          lv_s[o] = fminf(10.f, fmaxf(-10.f, acc));
    }
    __syncthreads();
    if (tid < ZD) {
        float m = mu_s[tid], lv = lv_s[tid];
        out[BB*TT*9 + b*ZD + tid] = m;
        out[BB*TT*9 + BB*ZD + b*ZD + tid] = lv;
        emb[tid] = m + eps[b*ZD+tid]*expf(0.5f*lv);
    }
    __syncthreads();
    {
        float acc = fcb[tid];
        const float* W = fcW + tid*ZD;
        for (int k = 0; k < ZD; k++) acc += W[k]*emb[k];
        xs[tid] = acc;
    }
    __syncthreads();
    for (int g = tid; g < GG; g += 256) {
        float acc = gbih[g];
        const float* W = gWih + (size_t)g*GH;
        for (int k = 0; k < XD; k++) acc += W[k]*xs[k];
        g_gxbase[b*GG+g] = acc;
    }
}

// K5: GRU scan + pipelined jf head. 928 threads, 2 batches/block, 2 syncs/step.
__global__ void __launch_bounds__(928) k_gru(
    const float* __restrict__ noise_eps,
    const float* __restrict__ gWih, const float* __restrict__ gWhh,
    const float* __restrict__ gbhh,
    const float* __restrict__ b1,
    const float* __restrict__ W2, const float* __restrict__ b2,
    float* __restrict__ out)
{
    extern __shared__ float sm[];
    ulonglong2* wsA = (ulonglong2*)sm;   // [16][784]: k=32..95 pair-pairs
    float* hb0  = sm + 50176;            // 264 (zero-padded)
    float* hb1  = hb0 + 264;
    float* sums = hb1 + 264;             // [2][784]
    float* ghn  = sums + 2*784;          // [2][264]
    float* f1s  = ghn + 2*264;           // [2][64]
    float* nsAll= f1s + 128;             // [TT][8]
    int tid = threadIdx.x;
    int b0 = blockIdx.x*2;

    for (int j = tid; j < 528; j += 928) hb0[j] = 0.f;
    for (int j = tid; j < TT*8; j += 928){
        int t = j >> 3, r = j & 7, bb = r >> 2, jj = r & 3;
        nsAll[j] = noise_eps[t*(BB*4) + (b0+bb)*4 + jj] * 0.1f;
    }

    unsigned long long wr2[16];
    float w260=0,wn0=0,wn1=0,wn2=0,wn3=0,wt=0,bh=0,gx0b=0,gx1b=0;
    if (tid < GG){
        const float* row = gWhh + (size_t)tid*GH;
#pragma unroll
        for (int i = 0; i < 16; i++)
            asm("mov.b64 %0, {%1,%2};" : "=l"(wr2[i]) : "f"(row[2*i]), "f"(row[2*i+1]));
#pragma unroll
        for (int i = 0; i < 16; i++){
            ulonglong2 w;
            asm("mov.b64 %0, {%1,%2};" : "=l"(w.x) : "f"(row[32+4*i]), "f"(row[33+4*i]));
            asm("mov.b64 %0, {%1,%2};" : "=l"(w.y) : "f"(row[34+4*i]), "f"(row[35+4*i]));
            wsA[i*784 + tid] = w;
        }
        w260 = row[260];
        const float* Wi = gWih + (size_t)tid*GH;
        wn0=Wi[256]; wn1=Wi[257]; wn2=Wi[258]; wn3=Wi[259]; wt=Wi[260];
        bh = gbhh[tid];
        gx0b = g_gxbase[b0*GG + tid];
        gx1b = g_gxbase[(b0+1)*GG + tid];
    }
    __syncthreads();
    const float inv = 1.0f/(float)(TT-1);
    for (int t = 0; t <= TT; t++){
        // ---- P1: matvec(t) || f1-head(t-1)
        if (t < TT && tid < GG){
            const float* nsp = nsAll + t*8;
            float tv = (float)t * inv;
            float gx0 = gx0b + wn0*nsp[0]+wn1*nsp[1]+wn2*nsp[2]+wn3*nsp[3] + wt*tv;
            float gx1 = gx1b + wn0*nsp[4]+wn1*nsp[5]+wn2*nsp[6]+wn3*nsp[7] + wt*tv;
            unsigned long long a0p = 0ull, a1p = 0ull;
            const ulonglong2* H0 = (const ulonglong2*)hb0;
            const ulonglong2* H1 = (const ulonglong2*)hb1;
#pragma unroll
            for (int i = 0; i < 8; i++){
                ulonglong2 h0 = H0[i], h1 = H1[i];
                fma2(a0p, wr2[2*i],   h0.x);  fma2(a1p, wr2[2*i],   h1.x);
                fma2(a0p, wr2[2*i+1], h0.y);  fma2(a1p, wr2[2*i+1], h1.y);
            }
#pragma unroll
            for (int i = 0; i < 16; i++){
                ulonglong2 w = wsA[i*784 + tid];
                ulonglong2 h0 = H0[8+i], h1 = H1[8+i];
                fma2(a0p, w.x, h0.x);  fma2(a1p, w.x, h1.x);
                fma2(a0p, w.y, h0.y);  fma2(a1p, w.y, h1.y);
            }
            const ulonglong2* wp = (const ulonglong2*)g_gWhh4 + tid;
#pragma unroll 8
            for (int p = 0; p < 41; p++){
                ulonglong2 w = wp[(size_t)p*GG];
                ulonglong2 h0 = H0[24+p], h1 = H1[24+p];
                fma2(a0p, w.x, h0.x);  fma2(a1p, w.x, h1.x);
                fma2(a0p, w.y, h0.y);  fma2(a1p, w.y, h1.y);
            }
            float s00,s01,s10,s11;
            asm("mov.b64 {%0,%1}, %2;" : "=f"(s00), "=f"(s01) : "l"(a0p));
            asm("mov.b64 {%0,%1}, %2;" : "=f"(s10), "=f"(s11) : "l"(a1p));
            float gh0 = bh + (s00+s01) + w260*hb0[260];
            float gh1 = bh + (s10+s11) + w260*hb1[260];
            float v0 = gx0 + gh0, v1 = gx1 + gh1;
            if (tid >= 522){
                v0 = gx0; v1 = gx1;
                ghn[tid-522] = gh0; ghn[264 + tid-522] = gh1;
            }
            sums[tid] = v0; sums[784 + tid] = v1;
        }
        if (t >= 1 && tid >= 800){
            int q = tid - 800, bb = q >> 6, o = q & 63;
            const float4* hv = (const float4*)(bb ? hb1 : hb0);
            const float4* Wv = g_W1T4 + o;
            float acc = b1[o];
#pragma unroll
            for (int p = 0; p < 66; p++){
                float4 w = Wv[p*ZD];
                float4 h = hv[p];
                acc += w.x*h.x + w.y*h.y + w.z*h.z + w.w*h.w;
            }
            f1s[bb*64 + o] = leakyf_(acc, 0.2f);
        }
        __syncthreads();
        // ---- P2: gates/update(t) || frame(t-1)
        if (t < TT && tid < 522){
            int bb = tid/261, j = tid - bb*261;
            float* hb = bb ? hb1 : hb0;
            const float* s = sums + bb*784;
            float r = sigmoidf_(s[j]);
            float z = sigmoidf_(s[261+j]);
            float n = tanhf(s[522+j] + r*ghn[bb*264 + j]);
            hb[j] = (1.f - z)*n + z*hb[j];
        }
        if (t >= 1 && tid >= 800 && tid < 818){
            int q = tid - 800, bb = q/9, i = q - bb*9;
            float acc = b2[i];
            const float* W = W2 + i*ZD;
            for (int o = 0; o < ZD; o++) acc += W[o]*f1s[bb*64 + o];
            out[(size_t)(b0+bb)*(TT*9) + (t-1)*9 + i] = sigmoidf_(acc);
        }
        __syncthreads();
    }
}

extern "C" void kernel_launch(void* const* d_in, const int* in_sizes, int n_in,
                              void* d_out, int out_size)
{
    const float* input_data = (const float*)d_in[0];
    const float* eps        = (const float*)d_in[1];
    const float* noise_eps  = (const float*)d_in[2];
    const float* proj_W     = (const float*)d_in[3];
    const float* proj_b     = (const float*)d_in[4];
    const float* lstm_Wih   = (const float*)d_in[5];
    const float* lstm_Whh   = (const float*)d_in[6];
    const float* lstm_bih   = (const float*)d_in[7];
    const float* lstm_bhh   = (const float*)d_in[8];
    const float* mu_W       = (const float*)d_in[9];
    const float* mu_b       = (const float*)d_in[10];
    const float* lv_W       = (const float*)d_in[11];
    const float* lv_b       = (const float*)d_in[12];
    const float* fcin_W     = (const float*)d_in[13];
    const float* fcin_b     = (const float*)d_in[14];
    const float* gru_Wih    = (const float*)d_in[15];
    const float* gru_Whh    = (const float*)d_in[16];
    const float* gru_bih    = (const float*)d_in[17];
    const float* gru_bhh    = (const float*)d_in[18];
    const float* jf_W1      = (const float*)d_in[19];
    const float* jf_b1      = (const float*)d_in[20];
    const float* jf_W2      = (const float*)d_in[21];
    const float* jf_b2      = (const float*)d_in[22];
    float* out = (float*)d_out;

    int gemm_smem = 2*2*128*SMSH*2;  // 73728 bytes
    int lstm_smem = 32768*4 + (128+512)*4;
    int gru_smem  = (50176 + 264 + 264 + 2*784 + 2*264 + 128 + TT*8)*4;
    cudaFuncSetAttribute(k_gemm, cudaFuncAttributeMaxDynamicSharedMemorySize, gemm_smem);
    cudaFuncSetAttribute(k_lstm, cudaFuncAttributeMaxDynamicSharedMemorySize, lstm_smem);
    cudaFuncSetAttribute(k_gru,  cudaFuncAttributeMaxDynamicSharedMemorySize, gru_smem);

    k_prep<<<160, 256>>>(lstm_Wih, gru_Whh, jf_W1);
    k_proj<<<BB*TT/8, 512>>>(input_data, proj_W, proj_b);
    dim3 g2(HG/128, TT*BB/128);   // (4, 100): bn fastest -> A-tile L2 reuse
    k_gemm<<<g2, 256, gemm_smem>>>(lstm_bih, lstm_bhh);
    k_lstm<<<BB, 512, lstm_smem>>>(lstm_Whh);
    k_head<<<BB, 256>>>(eps, mu_W, mu_b, lv_W, lv_b, fcin_W, fcin_b,
                        gru_Wih, gru_bih, out);
    k_gru<<<BB/2, 928, gru_smem>>>(noise_eps, gru_Wih, gru_Whh, gru_bhh,
                                   jf_b1, jf_W2, jf_b2, out);
}